// round 2
// baseline (speedup 1.0000x reference)
#include <cuda_runtime.h>

#define INV_SQRT2F 0.70710678118654752440f

// g_M[n][p4] = (Re M[2p4][n], Im M[2p4][n], Re M[2p4+1][n], Im M[2p4+1][n])
// i.e. column-n of the fixed 16x16 circuit unitary, two output rows per float4.
__device__ float4 g_M[16][8];
// g_W[r][p] = (sum_w lin_w[0][4r+w]*sign_w(p), sum_w lin_w[1][4r+w]*sign_w(p))
__device__ float2 g_W[4][16];

// ---------------------------------------------------------------------------
// Setup: build M = H4*D2 * H4*D1 * H4*D0 (16x16 complex) and the sign/lin_w
// fold table. One 256-thread block, negligible runtime.
// ---------------------------------------------------------------------------
__global__ void setup_kernel(const float* __restrict__ weights,
                             const float* __restrict__ lin_w) {
    __shared__ float2 M[16][16];   // [p][n] = <p|U|n>
    const int t = threadIdx.x;     // 256 threads
    const int p = t >> 4, n = t & 15;

    M[p][n] = make_float2(p == n ? 1.0f : 0.0f, 0.0f);
    __syncthreads();

    for (int l = 0; l < 3; ++l) {
        // CRZ ring layer: diagonal phase exp(i*theta(p))
        float th = 0.0f;
        #pragma unroll
        for (int i = 0; i < 4; ++i) {
            int bi = (p >> (3 - i)) & 1;                 // control = wire i
            int bj = (p >> (3 - ((i + 1) & 3))) & 1;     // target  = wire i+1
            th += (float)bi * (float)(2 * bj - 1) * weights[4 * l + i];
        }
        th *= 0.5f;
        float sr, cr;
        sincosf(th, &sr, &cr);
        float2 v = M[p][n];
        M[p][n] = make_float2(v.x * cr - v.y * sr, v.x * sr + v.y * cr);
        __syncthreads();
        // H on every wire (row mixing)
        for (int w = 0; w < 4; ++w) {
            int bp = 3 - w;
            if (((p >> bp) & 1) == 0) {
                int p1 = p | (1 << bp);
                float2 v0 = M[p][n], v1 = M[p1][n];
                M[p][n]  = make_float2((v0.x + v1.x) * INV_SQRT2F,
                                       (v0.y + v1.y) * INV_SQRT2F);
                M[p1][n] = make_float2((v0.x - v1.x) * INV_SQRT2F,
                                       (v0.y - v1.y) * INV_SQRT2F);
            }
            __syncthreads();
        }
    }

    // Export M transposed & packed: g_M[n][p4]
    if (t < 128) {
        int nn = t >> 3, p4 = t & 7;
        float2 a = M[2 * p4][nn], b = M[2 * p4 + 1][nn];
        g_M[nn][p4] = make_float4(a.x, a.y, b.x, b.y);
    }
    // Sign/lin_w fold: W_{k,r}[p] = sum_w lin_w[k][4r+w] * sign_w(p)
    if (t < 64) {
        int r = t >> 4, pp = t & 15;
        float w0 = 0.0f, w1 = 0.0f;
        #pragma unroll
        for (int w = 0; w < 4; ++w) {
            float sgn = ((pp >> (3 - w)) & 1) ? -1.0f : 1.0f;
            w0 += lin_w[4 * r + w] * sgn;
            w1 += lin_w[16 + 4 * r + w] * sgn;
        }
        g_W[r][pp] = make_float2(w0, w1);
    }
}

// ---------------------------------------------------------------------------
// Main kernel: one thread per sample. For each of the 4 sub-batches:
// build the real product state s = u01 (x) u23, brute-force complex matvec
// amp = M s, probs, fold into both logits. Then 2-way softmax.
// ---------------------------------------------------------------------------
__global__ void __launch_bounds__(256)
main_kernel(const float* __restrict__ x,
            const float* __restrict__ lin_b,
            float2* __restrict__ out, int bsz) {
    __shared__ float4 Msh[16][8];
    __shared__ float2 Wsh[4][16];
    if (threadIdx.x < 128) {
        int nn = threadIdx.x >> 3, p4 = threadIdx.x & 7;
        Msh[nn][p4] = g_M[nn][p4];
    }
    if (threadIdx.x < 64) {
        (&Wsh[0][0])[threadIdx.x] = (&g_W[0][0])[threadIdx.x];
    }
    __syncthreads();

    int b = blockIdx.x * blockDim.x + threadIdx.x;
    if (b >= bsz) return;

    float xv[16];
    const float4* xp = reinterpret_cast<const float4*>(x + (size_t)b * 16);
    #pragma unroll
    for (int i = 0; i < 4; ++i) {
        float4 v = xp[i];
        xv[4 * i + 0] = v.x; xv[4 * i + 1] = v.y;
        xv[4 * i + 2] = v.z; xv[4 * i + 3] = v.w;
    }

    float l0 = lin_b[0], l1 = lin_b[1];

    #pragma unroll
    for (int r = 0; r < 4; ++r) {
        // angle column j (wire j) of sub-batch r:
        //   flat x index = 8*(r>>1) + 4*(j>>1) + 2*(r&1) + (j&1)
        float cj[4], sj[4];
        #pragma unroll
        for (int j = 0; j < 4; ++j) {
            int idx = ((r >> 1) << 3) | ((j >> 1) << 2) | ((r & 1) << 1) | (j & 1);
            __sincosf(xv[idx] * 0.5f, &sj[j], &cj[j]);
        }
        // wire 0 -> bit3, wire 1 -> bit2, wire 2 -> bit1, wire 3 -> bit0
        float u01[4] = {cj[0]*cj[1], cj[0]*sj[1], sj[0]*cj[1], sj[0]*sj[1]};
        float u23[4] = {cj[2]*cj[3], cj[2]*sj[3], sj[2]*cj[3], sj[2]*sj[3]};

        float ar[16], ai[16];
        #pragma unroll
        for (int p = 0; p < 16; ++p) { ar[p] = 0.0f; ai[p] = 0.0f; }

        #pragma unroll
        for (int n = 0; n < 16; ++n) {
            float sn = u01[n >> 2] * u23[n & 3];
            #pragma unroll
            for (int p4 = 0; p4 < 8; ++p4) {
                float4 m = Msh[n][p4];
                ar[2 * p4]     += m.x * sn;
                ai[2 * p4]     += m.y * sn;
                ar[2 * p4 + 1] += m.z * sn;
                ai[2 * p4 + 1] += m.w * sn;
            }
        }

        #pragma unroll
        for (int p = 0; p < 16; ++p) {
            float prob = ar[p] * ar[p] + ai[p] * ai[p];
            float2 wv = Wsh[r][p];
            l0 += prob * wv.x;
            l1 += prob * wv.y;
        }
    }

    float m  = fmaxf(l0, l1);
    float e0 = __expf(l0 - m), e1 = __expf(l1 - m);
    float inv = __fdividef(1.0f, e0 + e1);
    out[b] = make_float2(e0 * inv, e1 * inv);
}

// ---------------------------------------------------------------------------
extern "C" void kernel_launch(void* const* d_in, const int* in_sizes, int n_in,
                              void* d_out, int out_size) {
    const float* x = nullptr;
    const float* weights = nullptr;
    const float* lin_w = nullptr;
    const float* lin_b = nullptr;
    for (int i = 0; i < n_in; ++i) {
        int sz = in_sizes[i];
        if (sz == 12)      weights = (const float*)d_in[i];
        else if (sz == 32) lin_w   = (const float*)d_in[i];
        else if (sz == 2)  lin_b   = (const float*)d_in[i];
        else               x       = (const float*)d_in[i];
    }
    int bsz = out_size / 2;
    setup_kernel<<<1, 256>>>(weights, lin_w);
    int threads = 256;
    int blocks  = (bsz + threads - 1) / threads;
    main_kernel<<<blocks, threads>>>(x, lin_b, (float2*)d_out, bsz);
}

// round 3
// speedup vs baseline: 27.6110x; 27.6110x over previous
#include <cuda_runtime.h>

#define INV_SQRT2F 0.70710678118654752440f

// Folded contraction table: E[r][P][Qpad] over the 10 symmetric index pairs,
// lanes = (logit0, logit1). Built correctness-by-construction in setup.
// Q padded 10->12 so rows are 16B-aligned (future float4 loads).
__device__ float2 g_E[4][10][12];

// ---------------------------------------------------------------------------
// Setup kernel (1 block x 256 threads, negligible):
// 1) M = H4*D2 * H4*D1 * H4*D0  (verified in round 2)
// 2) B_w[n][m] = sum_p sign_w(p) * Re(conj(M[p][n]) M[p][m])
// 3) E[r][P][Q] = sum over ordered tuples (a,b) in ord(P), (c,d) in ord(Q) of
//    C_{k,r}[4a+c][4b+d],  C_{k,r} = sum_w lin_w[k][4r+w] B_w
//    (pure re-indexing of s^T C s -- no multiplicity reasoning)
// ---------------------------------------------------------------------------
__global__ void setup_kernel(const float* __restrict__ weights,
                             const float* __restrict__ lin_w) {
    __shared__ float2 M[16][16];     // [p][n]
    __shared__ float  B[4][16][16];
    const int t = threadIdx.x;
    const int p = t >> 4, n = t & 15;

    M[p][n] = make_float2(p == n ? 1.0f : 0.0f, 0.0f);
    __syncthreads();

    for (int l = 0; l < 3; ++l) {
        float th = 0.0f;
        #pragma unroll
        for (int i = 0; i < 4; ++i) {
            int bi = (p >> (3 - i)) & 1;                 // control wire i
            int bj = (p >> (3 - ((i + 1) & 3))) & 1;     // target wire i+1
            th += (float)bi * (float)(2 * bj - 1) * weights[4 * l + i];
        }
        th *= 0.5f;
        float sr, cr;
        sincosf(th, &sr, &cr);
        float2 v = M[p][n];
        M[p][n] = make_float2(v.x * cr - v.y * sr, v.x * sr + v.y * cr);
        __syncthreads();
        for (int w = 0; w < 4; ++w) {
            int bp = 3 - w;
            if (((p >> bp) & 1) == 0) {
                int p1 = p | (1 << bp);
                float2 v0 = M[p][n], v1 = M[p1][n];
                M[p][n]  = make_float2((v0.x + v1.x) * INV_SQRT2F,
                                       (v0.y + v1.y) * INV_SQRT2F);
                M[p1][n] = make_float2((v0.x - v1.x) * INV_SQRT2F,
                                       (v0.y - v1.y) * INV_SQRT2F);
            }
            __syncthreads();
        }
    }

    // B_w[n][m]
    {
        const int nn = t >> 4, mm = t & 15;
        float d[16];
        #pragma unroll
        for (int pp = 0; pp < 16; ++pp)
            d[pp] = M[pp][nn].x * M[pp][mm].x + M[pp][nn].y * M[pp][mm].y;
        #pragma unroll
        for (int w = 0; w < 4; ++w) {
            float acc = 0.0f;
            #pragma unroll
            for (int pp = 0; pp < 16; ++pp) {
                float sgn = ((pp >> (3 - w)) & 1) ? -1.0f : 1.0f;
                acc += sgn * d[pp];
            }
            B[w][nn][mm] = acc;
        }
    }
    __syncthreads();

    // E table by explicit ordered-tuple enumeration.
    const int PA[10] = {0,0,0,0,1,1,1,2,2,3};
    const int PB[10] = {0,1,2,3,1,2,3,2,3,3};
    for (int e = t; e < 400; e += 256) {
        int r = e / 100, P = (e / 10) % 10, Q = e % 10;
        int pa = PA[P], pb = PB[P], qa = PA[Q], qb = PB[Q];
        int na = (pa == pb) ? 1 : 2;     // ordered (a,b) variants of P
        int nc = (qa == qb) ? 1 : 2;     // ordered (c,d) variants of Q
        float s0 = 0.0f, s1 = 0.0f;
        for (int ia = 0; ia < na; ++ia) {
            int a = ia ? pb : pa, b = ia ? pa : pb;
            for (int ic = 0; ic < nc; ++ic) {
                int c = ic ? qb : qa, d = ic ? qa : qb;
                float bv0 = 0.0f, bv1 = 0.0f;
                #pragma unroll
                for (int w = 0; w < 4; ++w) {
                    float Bw = B[w][4 * a + c][4 * b + d];
                    bv0 += lin_w[4 * r + w]      * Bw;
                    bv1 += lin_w[16 + 4 * r + w] * Bw;
                }
                s0 += bv0; s1 += bv1;
            }
        }
        g_E[r][P][Q] = make_float2(s0, s1);
    }
}

// ---------------------------------------------------------------------------
// Main kernel: one thread per sample. Per sub-batch r: 4 fast sincos,
// folded 10x10 bilinear contraction (both logits), then 2-way softmax.
// Low register pressure by design (no xv[16], no amp arrays).
// ---------------------------------------------------------------------------
__global__ void __launch_bounds__(256, 2)
main_kernel(const float* __restrict__ x,
            const float* __restrict__ lin_b,
            float2* __restrict__ out, int bsz) {
    __shared__ float2 Esh[4][10][12];
    {
        const float2* src = &g_E[0][0][0];
        float2* dst = &Esh[0][0][0];
        for (int i = threadIdx.x; i < 480; i += 256) dst[i] = src[i];
    }
    __syncthreads();

    int b = blockIdx.x * blockDim.x + threadIdx.x;
    if (b >= bsz) return;

    const float2* xp = reinterpret_cast<const float2*>(x) + (size_t)b * 8;

    float l0 = lin_b[0], l1 = lin_b[1];

    const int PA[10] = {0,0,0,0,1,1,1,2,2,3};
    const int PB[10] = {0,1,2,3,1,2,3,2,3,3};

    #pragma unroll
    for (int r = 0; r < 4; ++r) {
        // angles for sub-batch r live at flat indices base, base+1, base+4,
        // base+5 with base = 8*(r>>1) + 2*(r&1)  (two aligned float2 loads)
        const int base2 = ((r >> 1) << 2) | (r & 1);   // base/2
        float2 A = xp[base2];
        float2 Bv = xp[base2 + 2];

        float c0, s0, c1, s1, c2, s2, c3, s3;
        __sincosf(A.x  * 0.5f, &s0, &c0);
        __sincosf(A.y  * 0.5f, &s1, &c1);
        __sincosf(Bv.x * 0.5f, &s2, &c2);
        __sincosf(Bv.y * 0.5f, &s3, &c3);

        float u01[4] = {c0*c1, c0*s1, s0*c1, s0*s1};
        float u23[4] = {c2*c3, c2*s3, s2*c3, s2*s3};

        float g23[10];
        #pragma unroll
        for (int Q = 0; Q < 10; ++Q) g23[Q] = u23[PA[Q]] * u23[PB[Q]];

        #pragma unroll
        for (int P = 0; P < 10; ++P) {
            float t0 = 0.0f, t1 = 0.0f;
            #pragma unroll
            for (int Q = 0; Q < 10; ++Q) {
                float2 Ev = Esh[r][P][Q];
                t0 += Ev.x * g23[Q];
                t1 += Ev.y * g23[Q];
            }
            float g01 = u01[PA[P]] * u01[PB[P]];
            l0 += g01 * t0;
            l1 += g01 * t1;
        }
    }

    float m  = fmaxf(l0, l1);
    float e0 = __expf(l0 - m), e1 = __expf(l1 - m);
    float inv = __fdividef(1.0f, e0 + e1);
    out[b] = make_float2(e0 * inv, e1 * inv);
}

// ---------------------------------------------------------------------------
extern "C" void kernel_launch(void* const* d_in, const int* in_sizes, int n_in,
                              void* d_out, int out_size) {
    const float* x = nullptr;
    const float* weights = nullptr;
    const float* lin_w = nullptr;
    const float* lin_b = nullptr;
    for (int i = 0; i < n_in; ++i) {
        int sz = in_sizes[i];
        if (sz == 12)      weights = (const float*)d_in[i];
        else if (sz == 32) lin_w   = (const float*)d_in[i];
        else if (sz == 2)  lin_b   = (const float*)d_in[i];
        else               x       = (const float*)d_in[i];
    }
    int bsz = out_size / 2;
    setup_kernel<<<1, 256>>>(weights, lin_w);
    int threads = 256;
    int blocks  = (bsz + threads - 1) / threads;
    main_kernel<<<blocks, threads>>>(x, lin_b, (float2*)d_out, bsz);
}